// round 14
// baseline (speedup 1.0000x reference)
#include <cuda_runtime.h>
#include <cuda_bf16.h>
#include <cstdint>

#define B_N   32768
#define FIN   64
#define HID   32
#define E_N   25
#define HG    96
#define NBAND 12
#define NT2   4        // 64-row tiles per kernC block
#define SP2   204      // staging pitch (floats), divisible by 4 -> 16B-aligned rows

typedef unsigned long long u64;
typedef unsigned int u32;

// scratch (static device globals — no allocation)
__device__ float g_h2[B_N * HID];            // 4 MB
__device__ float g_part[1024][2 * HID];
__device__ float g_scale[HID];
__device__ float g_shift[HID];
__device__ u32   g_esplit[B_N * 32];         // per row 128B = bf16[64]: hi k0..31 | lo k0..31
__device__ u32   g_wsplit[NBAND * 256 * 32]; // per band 256 B-rows x 128B (same hi|lo layout)

__device__ __forceinline__ float selu_f(float x) {
    float p = 1.0507009873554805f * x;
    float n = 1.7580993408473766f * (__expf(x) - 1.0f);
    return x > 0.0f ? p : n;
}
__device__ __forceinline__ u64 pk2(float lo, float hi) {
    u64 r;
    asm("mov.b64 %0, {%1,%2};" : "=l"(r)
        : "r"(__float_as_uint(lo)), "r"(__float_as_uint(hi)));
    return r;
}
__device__ __forceinline__ void upk2(u64 v, float& lo, float& hi) {
    u32 a, b;
    asm("mov.b64 {%0,%1}, %2;" : "=r"(a), "=r"(b) : "l"(v));
    lo = __uint_as_float(a); hi = __uint_as_float(b);
}
#define FFMA2(d, a, b) asm("fma.rn.f32x2 %0, %1, %2, %0;" : "+l"(d) : "l"(a), "l"(b))

__device__ __forceinline__ uint16_t bf16b(float x) {
    __nv_bfloat16 h = __float2bfloat16(x);
    return *(uint16_t*)&h;
}
__device__ __forceinline__ float bf16f(uint16_t b) {
    __nv_bfloat16 h = *(__nv_bfloat16*)&b;
    return (float)h;
}

// warp-level bf16 MMA (HMMA), sm_80+ baseline — compiles for compute_103
__device__ __forceinline__ void mma16816(float* c, const u32* a, u32 b0, u32 b1) {
    asm volatile(
        "mma.sync.aligned.m16n8k16.row.col.f32.bf16.bf16.f32 "
        "{%0,%1,%2,%3}, {%4,%5,%6,%7}, {%8,%9}, {%0,%1,%2,%3};"
        : "+f"(c[0]), "+f"(c[1]), "+f"(c[2]), "+f"(c[3])
        : "r"(a[0]), "r"(a[1]), "r"(a[2]), "r"(a[3]), "r"(b0), "r"(b1));
}

// ---------------------------------------------------------------------------
// Kernel A: h = selu(X@W1+b1); h2 = h@W2+b2; store h2 + BN partials
// ---------------------------------------------------------------------------
__global__ void __launch_bounds__(128, 8) kernA(
    const float* __restrict__ X,
    const float* __restrict__ W1, const float* __restrict__ b1,
    const float* __restrict__ W2, const float* __restrict__ b2)
{
    extern __shared__ char sm[];
    float* xs  = (float*)sm;
    float* w1s = (float*)(sm + 8704);
    float* w2s = (float*)(sm + 8704 + 8192);
    float* b1s = (float*)(sm + 8704 + 8192 + 4096);
    float* b2s = b1s + HID;
    float* hs  = (float*)(sm + 8704 + 8192 + 4096 + 256);

    int t = threadIdx.x;
    int rowbase = blockIdx.x * 32;
    const float* Xb = X + (size_t)rowbase * FIN;

    #pragma unroll
    for (int j = 0; j < 4; j++) {
        int idx = t + j * 128;
        float4 v = ((const float4*)Xb)[idx];
        int row = idx >> 4, col = (idx & 15) * 4;
        *(float4*)&xs[row * 68 + col] = v;
    }
    #pragma unroll
    for (int j = 0; j < 4; j++) ((float4*)w1s)[t + j * 128] = ((const float4*)W1)[t + j * 128];
    #pragma unroll
    for (int j = 0; j < 2; j++) ((float4*)w2s)[t + j * 128] = ((const float4*)W2)[t + j * 128];
    if (t < HID) { b1s[t] = b1[t]; b2s[t] = b2[t]; }
    __syncthreads();

    int r  = t >> 2;
    int j0 = (t & 3) * 8;

    u64 acc[4];
    #pragma unroll
    for (int p = 0; p < 4; p++) acc[p] = *(const u64*)&b1s[j0 + 2 * p];
    #pragma unroll 8
    for (int k = 0; k < FIN; k++) {
        float xk = xs[r * 68 + k];
        u64 xv = pk2(xk, xk);
        ulonglong2 w0 = *(const ulonglong2*)&w1s[k * HID + j0];
        ulonglong2 w1v = *(const ulonglong2*)&w1s[k * HID + j0 + 4];
        FFMA2(acc[0], xv, w0.x);
        FFMA2(acc[1], xv, w0.y);
        FFMA2(acc[2], xv, w1v.x);
        FFMA2(acc[3], xv, w1v.y);
    }
    float hv[8];
    #pragma unroll
    for (int p = 0; p < 4; p++) {
        float a, b; upk2(acc[p], a, b);
        hv[2 * p] = selu_f(a); hv[2 * p + 1] = selu_f(b);
    }
    *(float4*)&hs[r * 36 + j0]     = make_float4(hv[0], hv[1], hv[2], hv[3]);
    *(float4*)&hs[r * 36 + j0 + 4] = make_float4(hv[4], hv[5], hv[6], hv[7]);
    __syncthreads();

    u64 acc2[4];
    #pragma unroll
    for (int p = 0; p < 4; p++) acc2[p] = *(const u64*)&b2s[j0 + 2 * p];
    #pragma unroll 8
    for (int k = 0; k < HID; k++) {
        float hk = hs[r * 36 + k];
        u64 hvv = pk2(hk, hk);
        ulonglong2 w0 = *(const ulonglong2*)&w2s[k * HID + j0];
        ulonglong2 w1v = *(const ulonglong2*)&w2s[k * HID + j0 + 4];
        FFMA2(acc2[0], hvv, w0.x);
        FFMA2(acc2[1], hvv, w0.y);
        FFMA2(acc2[2], hvv, w1v.x);
        FFMA2(acc2[3], hvv, w1v.y);
    }
    float o[8];
    #pragma unroll
    for (int p = 0; p < 4; p++) upk2(acc2[p], o[2 * p], o[2 * p + 1]);

    float* H2r = g_h2 + (size_t)(rowbase + r) * HID + j0;
    *(float4*)H2r       = make_float4(o[0], o[1], o[2], o[3]);
    *(float4*)(H2r + 4) = make_float4(o[4], o[5], o[6], o[7]);

    __syncthreads();
    *(float4*)&hs[r * 36 + j0]     = make_float4(o[0], o[1], o[2], o[3]);
    *(float4*)&hs[r * 36 + j0 + 4] = make_float4(o[4], o[5], o[6], o[7]);
    __syncthreads();

    if (t < HID) {
        float s = 0.f, s2 = 0.f;
        #pragma unroll 8
        for (int rr = 0; rr < 32; rr++) {
            float v = hs[rr * 36 + t];
            s += v; s2 += v * v;
        }
        g_part[blockIdx.x][t]       = s;
        g_part[blockIdx.x][HID + t] = s2;
    }
}

// ---------------------------------------------------------------------------
// Kernel B: fold partials -> scale/shift
// ---------------------------------------------------------------------------
__global__ void kernB(const float* __restrict__ gamma, const float* __restrict__ beta) {
    __shared__ float ps[8][64];
    int t = threadIdx.x;
    int c = t & 31, ch = t >> 5;
    float s = 0.f, s2 = 0.f;
    #pragma unroll 4
    for (int b = ch * 128; b < ch * 128 + 128; b++) {
        s  += g_part[b][c];
        s2 += g_part[b][HID + c];
    }
    ps[ch][c] = s; ps[ch][HID + c] = s2;
    __syncthreads();
    if (t < HID) {
        float S = 0.f, S2 = 0.f;
        #pragma unroll
        for (int ch2 = 0; ch2 < 8; ch2++) { S += ps[ch2][t]; S2 += ps[ch2][HID + t]; }
        float mu  = S  * (1.0f / B_N);
        float var = S2 * (1.0f / B_N) - mu * mu;
        float sc  = gamma[t] * rsqrtf(var + 1e-5f);
        g_scale[t] = sc;
        g_shift[t] = beta[t] - mu * sc;
    }
}

// ---------------------------------------------------------------------------
// Kernel E: e = selu(BN(h2)) -> bf16 hi/lo split -> g_esplit (half-row/thread)
// ---------------------------------------------------------------------------
__global__ void __launch_bounds__(128) kernE() {
    int idx = blockIdx.x * 128 + threadIdx.x;     // 0 .. 2*B_N-1
    int row = idx >> 1;
    int qb  = (idx & 1) * 4;
    const float4* hp = (const float4*)(g_h2 + (size_t)row * HID);
    u32 wh[8], wl[8];
    #pragma unroll
    for (int qq = 0; qq < 4; qq++) {
        int q = qb + qq;
        float4 v = hp[q];
        float e0 = selu_f(fmaf(v.x, g_scale[4 * q + 0], g_shift[4 * q + 0]));
        float e1 = selu_f(fmaf(v.y, g_scale[4 * q + 1], g_shift[4 * q + 1]));
        float e2 = selu_f(fmaf(v.z, g_scale[4 * q + 2], g_shift[4 * q + 2]));
        float e3 = selu_f(fmaf(v.w, g_scale[4 * q + 3], g_shift[4 * q + 3]));
        uint16_t h0 = bf16b(e0), h1 = bf16b(e1), h2v = bf16b(e2), h3 = bf16b(e3);
        wh[2 * qq]     = (u32)h0 | ((u32)h1 << 16);
        wh[2 * qq + 1] = (u32)h2v | ((u32)h3 << 16);
        uint16_t l0 = bf16b(e0 - bf16f(h0)), l1 = bf16b(e1 - bf16f(h1));
        uint16_t l2 = bf16b(e2 - bf16f(h2v)), l3 = bf16b(e3 - bf16f(h3));
        wl[2 * qq]     = (u32)l0 | ((u32)l1 << 16);
        wl[2 * qq + 1] = (u32)l2 | ((u32)l3 << 16);
    }
    uint4* op = (uint4*)g_esplit + (size_t)row * 8;
    int hb = qb >> 1;
    op[hb]     = make_uint4(wh[0], wh[1], wh[2], wh[3]);
    op[hb + 1] = make_uint4(wh[4], wh[5], wh[6], wh[7]);
    op[4 + hb]     = make_uint4(wl[0], wl[1], wl[2], wl[3]);
    op[4 + hb + 1] = make_uint4(wl[4], wl[5], wl[6], wl[7]);
}

// ---------------------------------------------------------------------------
// Kernel W: weight bf16 hi/lo split -> g_wsplit
// ---------------------------------------------------------------------------
__global__ void __launch_bounds__(256) kernW(const float* __restrict__ Wh) {
    int band = blockIdx.x;
    int t = threadIdx.x;
    int hgl = t >> 5, j = t & 31;
    u32 w[32];
    #pragma unroll
    for (int i = 0; i < 32; i++) w[i] = 0u;
    if (j < E_N) {
        const float* src = Wh + ((size_t)(band * 8 + hgl) * HID) * E_N + j;
        #pragma unroll
        for (int ww = 0; ww < 16; ww++) {
            float v0 = src[(2 * ww) * E_N];
            float v1 = src[(2 * ww + 1) * E_N];
            uint16_t h0 = bf16b(v0), h1 = bf16b(v1);
            w[ww] = (u32)h0 | ((u32)h1 << 16);
            uint16_t l0 = bf16b(v0 - bf16f(h0)), l1 = bf16b(v1 - bf16f(h1));
            w[16 + ww] = (u32)l0 | ((u32)l1 << 16);
        }
    }
    uint4* dst = (uint4*)g_wsplit + ((size_t)band * 256 + t) * 8;
    #pragma unroll
    for (int q = 0; q < 8; q++)
        dst[q] = make_uint4(w[4 * q], w[4 * q + 1], w[4 * q + 2], w[4 * q + 3]);
}

// ---------------------------------------------------------------------------
// Kernel C: full-band blocks. D = e-split x w-split via mma.sync bf16
// (hi*hi + hi*lo + lo*hi), bias + SELU + per-head L1-norm, compact staging ->
// 800B sector-aligned coalesced float4 store runs.
// grid (12 bands, 128) x 512 threads (16 warps); NT2=4 tiles of 64 rows.
// warp: mw = wid&3 (16 rows), nw = wid>>5.. wid>>2 (2 heads = 64 padded cols).
// smem: B[256][144B] @0 | bhs[256]f @36864 | A[64][144B] @37888 | stg[64][SP2] @47104
// total 99328 B -> 1 block/SM.
// ---------------------------------------------------------------------------
__global__ void __launch_bounds__(512) kernC(const float* __restrict__ bh,
                                             float* __restrict__ out)
{
    extern __shared__ char sm[];
    u32* Bs32  = (u32*)sm;               // 256 n-rows, stride 36 u32
    float* bhs = (float*)(sm + 36864);   // [256]
    u32* As32  = (u32*)(sm + 37888);     // 64 rows, stride 36 u32
    float* stg = (float*)(sm + 47104);   // [64][SP2]

    int t = threadIdx.x;
    int wid = t >> 5, lane = t & 31;
    int g = lane >> 2, tq = lane & 3;
    int band = blockIdx.x;
    int mw = wid & 3, nw = wid >> 2;     // m-tile, n-group (2 heads)
    int m0 = mw * 16;
    int lr0 = m0 + g;

    // B fill (once): 256 rows x 8 uint4
    {
        const uint4* srcB = (const uint4*)g_wsplit + (size_t)band * 2048;
        #pragma unroll
        for (int i = t; i < 2048; i += 512) {
            int r = i >> 3, j = i & 7;
            *(uint4*)(sm + r * 144 + j * 16) = srcB[i];
        }
    }
    if (t < 256) {
        int hgl = t >> 5, j = t & 31;
        bhs[t] = (j < E_N) ? bh[(band * 8 + hgl) * E_N + j] : 0.0f;
    }

    int row0 = blockIdx.y * (NT2 * 64);
    for (int tile = 0; tile < NT2; tile++) {
        // A fill: 64 rows x 8 uint4 = 512 (one per thread)
        {
            const uint4* srcA = (const uint4*)g_esplit + (size_t)row0 * 8;
            int r = t >> 3, j = t & 7;
            *(uint4*)(sm + 37888 + r * 144 + j * 16) = srcA[t];
        }
        __syncthreads();   // A (+ B/bias on tile 0) visible; prev store reads done

        // A fragments: 4 k-blocks of 16 (kb 0,1 = hi; 2,3 = lo)
        u32 aa[4][4];
        #pragma unroll
        for (int kb = 0; kb < 4; kb++) {
            int base = kb * 8 + tq;
            aa[kb][0] = As32[(m0 + g) * 36 + base];
            aa[kb][1] = As32[(m0 + g + 8) * 36 + base];
            aa[kb][2] = As32[(m0 + g) * 36 + base + 4];
            aa[kb][3] = As32[(m0 + g + 8) * 36 + base + 4];
        }

        float c[8][4];
        #pragma unroll
        for (int nt = 0; nt < 8; nt++)
            #pragma unroll
            for (int q = 0; q < 4; q++) c[nt][q] = 0.0f;

        #pragma unroll
        for (int nt = 0; nt < 8; nt++) {
            int nb = (nw * 64 + nt * 8 + g) * 36 + tq;
            u32 b00 = Bs32[nb],      b01 = Bs32[nb + 4];
            u32 b10 = Bs32[nb + 8],  b11 = Bs32[nb + 12];
            u32 b20 = Bs32[nb + 16], b21 = Bs32[nb + 20];
            u32 b30 = Bs32[nb + 24], b31 = Bs32[nb + 28];
            mma16816(c[nt], aa[0], b00, b01);   // hi*hi
            mma16816(c[nt], aa[1], b10, b11);
            mma16816(c[nt], aa[0], b20, b21);   // hi*lo
            mma16816(c[nt], aa[1], b30, b31);
            mma16816(c[nt], aa[2], b00, b01);   // lo*hi
            mma16816(c[nt], aa[3], b10, b11);
        }

        // epilogue in place: bias + selu + per-head abs row sums
        // head0 = 2nw (nt 0..3), head1 = 2nw+1 (nt 4..7)
        float s0g = 0.f, s0h = 0.f, s1g = 0.f, s1h = 0.f;
        #pragma unroll
        for (int nt = 0; nt < 8; nt++) {
            float b0v = bhs[nw * 64 + nt * 8 + 2 * tq];
            float b1v = bhs[nw * 64 + nt * 8 + 2 * tq + 1];
            c[nt][0] = selu_f(c[nt][0] + b0v);
            c[nt][1] = selu_f(c[nt][1] + b1v);
            c[nt][2] = selu_f(c[nt][2] + b0v);
            c[nt][3] = selu_f(c[nt][3] + b1v);
            if (nt < 4) { s0g += fabsf(c[nt][0]) + fabsf(c[nt][1]);
                          s0h += fabsf(c[nt][2]) + fabsf(c[nt][3]); }
            else        { s1g += fabsf(c[nt][0]) + fabsf(c[nt][1]);
                          s1h += fabsf(c[nt][2]) + fabsf(c[nt][3]); }
        }
        s0g += __shfl_xor_sync(0xFFFFFFFF, s0g, 1);
        s0g += __shfl_xor_sync(0xFFFFFFFF, s0g, 2);
        s0h += __shfl_xor_sync(0xFFFFFFFF, s0h, 1);
        s0h += __shfl_xor_sync(0xFFFFFFFF, s0h, 2);
        s1g += __shfl_xor_sync(0xFFFFFFFF, s1g, 1);
        s1g += __shfl_xor_sync(0xFFFFFFFF, s1g, 2);
        s1h += __shfl_xor_sync(0xFFFFFFFF, s1h, 1);
        s1h += __shfl_xor_sync(0xFFFFFFFF, s1h, 2);
        float inv0g = __fdividef(1.0f, fmaxf(s0g, 1e-12f));
        float inv0h = __fdividef(1.0f, fmaxf(s0h, 1e-12f));
        float inv1g = __fdividef(1.0f, fmaxf(s1g, 1e-12f));
        float inv1h = __fdividef(1.0f, fmaxf(s1h, 1e-12f));

        // stage compact: head hgl -> cols hgl*25 .. hgl*25+24
        #pragma unroll
        for (int nt = 0; nt < 8; nt++) {
            float ig = (nt < 4) ? inv0g : inv1g;
            float ih = (nt < 4) ? inv0h : inv1h;
            int bj   = (nt & 3) * 8 + 2 * tq;
            int hgl  = 2 * nw + (nt >> 2);
            int dcol = hgl * E_N + bj;
            if (bj < E_N) {
                stg[lr0 * SP2 + dcol]       = c[nt][0] * ig;  // sign(d)*|d|/l1 == d/l1
                stg[(lr0 + 8) * SP2 + dcol] = c[nt][2] * ih;
            }
            if (bj + 1 < E_N) {
                stg[lr0 * SP2 + dcol + 1]       = c[nt][1] * ig;
                stg[(lr0 + 8) * SP2 + dcol + 1] = c[nt][3] * ih;
            }
        }
        __syncthreads();   // stg visible

        // stores: 64 rows x 50 float4 = 800B sector-aligned runs per row
        float* ob = out + (size_t)row0 * (HG * E_N) + band * 200;
        #pragma unroll
        for (int i = t; i < 64 * 50; i += 512) {
            int r = i / 50, q = i - r * 50;
            float4 v = *(const float4*)&stg[r * SP2 + 4 * q];   // 16B-aligned (SP2%4==0)
            *(float4*)(ob + (size_t)r * (HG * E_N) + 4 * q) = v; // 16B-aligned (800B base)
        }
        __syncthreads();   // stg reads done before next tile's staging writes
        row0 += 64;
    }
}

// ---------------------------------------------------------------------------
extern "C" void kernel_launch(void* const* d_in, const int* in_sizes, int n_in,
                              void* d_out, int out_size) {
    const float* X     = (const float*)d_in[0];
    const float* W1    = (const float*)d_in[1];
    const float* b1    = (const float*)d_in[2];
    const float* W2    = (const float*)d_in[3];
    const float* b2    = (const float*)d_in[4];
    const float* gamma = (const float*)d_in[5];
    const float* beta  = (const float*)d_in[6];
    const float* Wh    = (const float*)d_in[7];
    const float* bh    = (const float*)d_in[8];
    float* out = (float*)d_out;

    cudaFuncSetAttribute(kernA, cudaFuncAttributeMaxDynamicSharedMemorySize, 25856);
    cudaFuncSetAttribute(kernC, cudaFuncAttributeMaxDynamicSharedMemorySize, 99328);

    kernA<<<1024, 128, 25856>>>(X, W1, b1, W2, b2);
    kernB<<<1, 256>>>(gamma, beta);
    kernW<<<NBAND, 256>>>(Wh);
    kernE<<<512, 128>>>();
    kernC<<<dim3(NBAND, 128), 512, 99328>>>(bh, out);
}

// round 17
// speedup vs baseline: 1.2135x; 1.2135x over previous
#include <cuda_runtime.h>
#include <cuda_bf16.h>
#include <cstdint>

#define B_N   32768
#define FIN   64
#define HID   32
#define E_N   25
#define HG    96
#define NBAND 12
#define NT2   4        // row-tiles (128 rows each) per kernC block

typedef unsigned long long u64;
typedef unsigned int u32;

// scratch (static device globals — no allocation)
__device__ float g_h2[B_N * HID];            // 4 MB
__device__ float g_part[1024][2 * HID];
__device__ float g_scale[HID];
__device__ float g_shift[HID];
__device__ u32   g_esplit[B_N * 32];         // per row 128B = bf16[64]: hi k0..31 | lo k0..31
__device__ u32   g_wsplit[NBAND * 256 * 32]; // per band 256 B-rows x 128B (same hi|lo layout)

__device__ __forceinline__ float selu_f(float x) {
    float p = 1.0507009873554805f * x;
    float n = 1.7580993408473766f * (__expf(x) - 1.0f);
    return x > 0.0f ? p : n;
}
__device__ __forceinline__ u64 pk2(float lo, float hi) {
    u64 r;
    asm("mov.b64 %0, {%1,%2};" : "=l"(r)
        : "r"(__float_as_uint(lo)), "r"(__float_as_uint(hi)));
    return r;
}
__device__ __forceinline__ void upk2(u64 v, float& lo, float& hi) {
    u32 a, b;
    asm("mov.b64 {%0,%1}, %2;" : "=r"(a), "=r"(b) : "l"(v));
    lo = __uint_as_float(a); hi = __uint_as_float(b);
}
#define FFMA2(d, a, b) asm("fma.rn.f32x2 %0, %1, %2, %0;" : "+l"(d) : "l"(a), "l"(b))

__device__ __forceinline__ uint16_t bf16b(float x) {
    __nv_bfloat16 h = __float2bfloat16(x);
    return *(uint16_t*)&h;
}
__device__ __forceinline__ float bf16f(uint16_t b) {
    __nv_bfloat16 h = *(__nv_bfloat16*)&b;
    return (float)h;
}

// warp-level bf16 MMA (HMMA), sm_80+ baseline — compiles for compute_103
__device__ __forceinline__ void mma16816(float* c, const u32* a, u32 b0, u32 b1) {
    asm volatile(
        "mma.sync.aligned.m16n8k16.row.col.f32.bf16.bf16.f32 "
        "{%0,%1,%2,%3}, {%4,%5,%6,%7}, {%8,%9}, {%0,%1,%2,%3};"
        : "+f"(c[0]), "+f"(c[1]), "+f"(c[2]), "+f"(c[3])
        : "r"(a[0]), "r"(a[1]), "r"(a[2]), "r"(a[3]), "r"(b0), "r"(b1));
}

// ---------------------------------------------------------------------------
// Kernel A: h = selu(X@W1+b1); h2 = h@W2+b2; store h2 + BN partials
// ---------------------------------------------------------------------------
__global__ void __launch_bounds__(128, 8) kernA(
    const float* __restrict__ X,
    const float* __restrict__ W1, const float* __restrict__ b1,
    const float* __restrict__ W2, const float* __restrict__ b2)
{
    extern __shared__ char sm[];
    float* xs  = (float*)sm;
    float* w1s = (float*)(sm + 8704);
    float* w2s = (float*)(sm + 8704 + 8192);
    float* b1s = (float*)(sm + 8704 + 8192 + 4096);
    float* b2s = b1s + HID;
    float* hs  = (float*)(sm + 8704 + 8192 + 4096 + 256);

    int t = threadIdx.x;
    int rowbase = blockIdx.x * 32;
    const float* Xb = X + (size_t)rowbase * FIN;

    #pragma unroll
    for (int j = 0; j < 4; j++) {
        int idx = t + j * 128;
        float4 v = ((const float4*)Xb)[idx];
        int row = idx >> 4, col = (idx & 15) * 4;
        *(float4*)&xs[row * 68 + col] = v;
    }
    #pragma unroll
    for (int j = 0; j < 4; j++) ((float4*)w1s)[t + j * 128] = ((const float4*)W1)[t + j * 128];
    #pragma unroll
    for (int j = 0; j < 2; j++) ((float4*)w2s)[t + j * 128] = ((const float4*)W2)[t + j * 128];
    if (t < HID) { b1s[t] = b1[t]; b2s[t] = b2[t]; }
    __syncthreads();

    int r  = t >> 2;
    int j0 = (t & 3) * 8;

    u64 acc[4];
    #pragma unroll
    for (int p = 0; p < 4; p++) acc[p] = *(const u64*)&b1s[j0 + 2 * p];
    #pragma unroll 8
    for (int k = 0; k < FIN; k++) {
        float xk = xs[r * 68 + k];
        u64 xv = pk2(xk, xk);
        ulonglong2 w0 = *(const ulonglong2*)&w1s[k * HID + j0];
        ulonglong2 w1v = *(const ulonglong2*)&w1s[k * HID + j0 + 4];
        FFMA2(acc[0], xv, w0.x);
        FFMA2(acc[1], xv, w0.y);
        FFMA2(acc[2], xv, w1v.x);
        FFMA2(acc[3], xv, w1v.y);
    }
    float hv[8];
    #pragma unroll
    for (int p = 0; p < 4; p++) {
        float a, b; upk2(acc[p], a, b);
        hv[2 * p] = selu_f(a); hv[2 * p + 1] = selu_f(b);
    }
    *(float4*)&hs[r * 36 + j0]     = make_float4(hv[0], hv[1], hv[2], hv[3]);
    *(float4*)&hs[r * 36 + j0 + 4] = make_float4(hv[4], hv[5], hv[6], hv[7]);
    __syncthreads();

    u64 acc2[4];
    #pragma unroll
    for (int p = 0; p < 4; p++) acc2[p] = *(const u64*)&b2s[j0 + 2 * p];
    #pragma unroll 8
    for (int k = 0; k < HID; k++) {
        float hk = hs[r * 36 + k];
        u64 hvv = pk2(hk, hk);
        ulonglong2 w0 = *(const ulonglong2*)&w2s[k * HID + j0];
        ulonglong2 w1v = *(const ulonglong2*)&w2s[k * HID + j0 + 4];
        FFMA2(acc2[0], hvv, w0.x);
        FFMA2(acc2[1], hvv, w0.y);
        FFMA2(acc2[2], hvv, w1v.x);
        FFMA2(acc2[3], hvv, w1v.y);
    }
    float o[8];
    #pragma unroll
    for (int p = 0; p < 4; p++) upk2(acc2[p], o[2 * p], o[2 * p + 1]);

    float* H2r = g_h2 + (size_t)(rowbase + r) * HID + j0;
    *(float4*)H2r       = make_float4(o[0], o[1], o[2], o[3]);
    *(float4*)(H2r + 4) = make_float4(o[4], o[5], o[6], o[7]);

    __syncthreads();
    *(float4*)&hs[r * 36 + j0]     = make_float4(o[0], o[1], o[2], o[3]);
    *(float4*)&hs[r * 36 + j0 + 4] = make_float4(o[4], o[5], o[6], o[7]);
    __syncthreads();

    if (t < HID) {
        float s = 0.f, s2 = 0.f;
        #pragma unroll 8
        for (int rr = 0; rr < 32; rr++) {
            float v = hs[rr * 36 + t];
            s += v; s2 += v * v;
        }
        g_part[blockIdx.x][t]       = s;
        g_part[blockIdx.x][HID + t] = s2;
    }
}

// ---------------------------------------------------------------------------
// Kernel BW: block 0 = fold partials -> scale/shift; blocks 1..12 = weight split
// (fusion keeps launch count at 4 so kernC lands in the ncu capture slot)
// ---------------------------------------------------------------------------
__global__ void __launch_bounds__(256) kernBW(
    const float* __restrict__ gamma, const float* __restrict__ beta,
    const float* __restrict__ Wh)
{
    int t = threadIdx.x;
    if (blockIdx.x == 0) {
        __shared__ float ps[8][64];
        int c = t & 31, ch = t >> 5;
        float s = 0.f, s2 = 0.f;
        #pragma unroll 4
        for (int b = ch * 128; b < ch * 128 + 128; b++) {
            s  += g_part[b][c];
            s2 += g_part[b][HID + c];
        }
        ps[ch][c] = s; ps[ch][HID + c] = s2;
        __syncthreads();
        if (t < HID) {
            float S = 0.f, S2 = 0.f;
            #pragma unroll
            for (int ch2 = 0; ch2 < 8; ch2++) { S += ps[ch2][t]; S2 += ps[ch2][HID + t]; }
            float mu  = S  * (1.0f / B_N);
            float var = S2 * (1.0f / B_N) - mu * mu;
            float sc  = gamma[t] * rsqrtf(var + 1e-5f);
            g_scale[t] = sc;
            g_shift[t] = beta[t] - mu * sc;
        }
    } else {
        int band = blockIdx.x - 1;
        int hgl = t >> 5, j = t & 31;
        u32 w[32];
        #pragma unroll
        for (int i = 0; i < 32; i++) w[i] = 0u;
        if (j < E_N) {
            const float* src = Wh + ((size_t)(band * 8 + hgl) * HID) * E_N + j;
            #pragma unroll
            for (int ww = 0; ww < 16; ww++) {
                float v0 = src[(2 * ww) * E_N];
                float v1 = src[(2 * ww + 1) * E_N];
                uint16_t h0 = bf16b(v0), h1 = bf16b(v1);
                w[ww] = (u32)h0 | ((u32)h1 << 16);
                uint16_t l0 = bf16b(v0 - bf16f(h0)), l1 = bf16b(v1 - bf16f(h1));
                w[16 + ww] = (u32)l0 | ((u32)l1 << 16);
            }
        }
        uint4* dst = (uint4*)g_wsplit + ((size_t)band * 256 + t) * 8;
        #pragma unroll
        for (int q = 0; q < 8; q++)
            dst[q] = make_uint4(w[4 * q], w[4 * q + 1], w[4 * q + 2], w[4 * q + 3]);
    }
}

// ---------------------------------------------------------------------------
// Kernel E: e = selu(BN(h2)) -> bf16 hi/lo split -> g_esplit (half-row/thread)
// ---------------------------------------------------------------------------
__global__ void __launch_bounds__(128) kernE() {
    int idx = blockIdx.x * 128 + threadIdx.x;     // 0 .. 2*B_N-1
    int row = idx >> 1;
    int qb  = (idx & 1) * 4;
    const float4* hp = (const float4*)(g_h2 + (size_t)row * HID);
    u32 wh[8], wl[8];
    #pragma unroll
    for (int qq = 0; qq < 4; qq++) {
        int q = qb + qq;
        float4 v = hp[q];
        float e0 = selu_f(fmaf(v.x, g_scale[4 * q + 0], g_shift[4 * q + 0]));
        float e1 = selu_f(fmaf(v.y, g_scale[4 * q + 1], g_shift[4 * q + 1]));
        float e2 = selu_f(fmaf(v.z, g_scale[4 * q + 2], g_shift[4 * q + 2]));
        float e3 = selu_f(fmaf(v.w, g_scale[4 * q + 3], g_shift[4 * q + 3]));
        uint16_t h0 = bf16b(e0), h1 = bf16b(e1), h2v = bf16b(e2), h3 = bf16b(e3);
        wh[2 * qq]     = (u32)h0 | ((u32)h1 << 16);
        wh[2 * qq + 1] = (u32)h2v | ((u32)h3 << 16);
        uint16_t l0 = bf16b(e0 - bf16f(h0)), l1 = bf16b(e1 - bf16f(h1));
        uint16_t l2 = bf16b(e2 - bf16f(h2v)), l3 = bf16b(e3 - bf16f(h3));
        wl[2 * qq]     = (u32)l0 | ((u32)l1 << 16);
        wl[2 * qq + 1] = (u32)l2 | ((u32)l3 << 16);
    }
    uint4* op = (uint4*)g_esplit + (size_t)row * 8;
    int hb = qb >> 1;
    op[hb]     = make_uint4(wh[0], wh[1], wh[2], wh[3]);
    op[hb + 1] = make_uint4(wh[4], wh[5], wh[6], wh[7]);
    op[4 + hb]     = make_uint4(wl[0], wl[1], wl[2], wl[3]);
    op[4 + hb + 1] = make_uint4(wl[4], wl[5], wl[6], wl[7]);
}

// ---------------------------------------------------------------------------
// Kernel C (R11 champion): D = e-split x w-split via mma.sync bf16
// (hi*hi + hi*lo + lo*hi), bias + SELU + per-head L1-normalize,
// compact staging -> coalesced float2 stores.
// grid (48 head-pairs, 64) x 256 threads; NT2=4 tiles of 128 rows per block.
// smem: B[64][144B] @0 | bhs[64]f @9216 | A[128][144B] @9472 (stg[64][68] aliases A)
// ---------------------------------------------------------------------------
__global__ void __launch_bounds__(256, 3) kernC(const float* __restrict__ bh,
                                                float* __restrict__ out)
{
    extern __shared__ char sm[];
    u32* Bs32  = (u32*)sm;               // row stride 36 u32
    float* bhs = (float*)(sm + 9216);    // [64]
    u32* As32  = (u32*)(sm + 9472);      // row stride 36 u32
    float* stg = (float*)(sm + 9472);    // [64][68] alias over A (post-MMA)

    int t = threadIdx.x;
    int wid = t >> 5, lane = t & 31;
    int g = lane >> 2, tq = lane & 3;
    int band = blockIdx.x >> 2, hp = blockIdx.x & 3;
    int m0 = wid * 16;
    int halfw = wid >> 2;                // which 64-row half this warp's rows are in
    int lr0 = (m0 & 63) + g;             // local row within half

    // B fill (once): 64 rows x 8 uint4
    {
        const uint4* srcB = (const uint4*)g_wsplit + ((size_t)band * 256 + hp * 64) * 8;
        #pragma unroll
        for (int i = t; i < 512; i += 256) {
            int r = i >> 3, j = i & 7;
            *(uint4*)(sm + r * 144 + j * 16) = srcB[i];
        }
    }
    if (t < 64) {
        int hh = t >> 5, j = t & 31;
        int head = band * 8 + hp * 2 + hh;
        bhs[t] = (j < E_N) ? bh[head * E_N + j] : 0.0f;
    }

    int row0 = blockIdx.y * (NT2 * 128);
    for (int tile = 0; tile < NT2; tile++) {
        // A fill: 128 rows x 8 uint4
        {
            const uint4* srcA = (const uint4*)g_esplit + (size_t)row0 * 8;
            #pragma unroll
            for (int i = t; i < 1024; i += 256) {
                int r = i >> 3, j = i & 7;
                *(uint4*)(sm + 9472 + r * 144 + j * 16) = srcA[i];
            }
        }
        __syncthreads();   // A (+ B/bias on tile 0) visible

        // A fragments: 4 k-blocks of 16 (kb 0,1 = hi; 2,3 = lo)
        u32 aa[4][4];
        #pragma unroll
        for (int kb = 0; kb < 4; kb++) {
            int base = kb * 8 + tq;
            aa[kb][0] = As32[(m0 + g) * 36 + base];
            aa[kb][1] = As32[(m0 + g + 8) * 36 + base];
            aa[kb][2] = As32[(m0 + g) * 36 + base + 4];
            aa[kb][3] = As32[(m0 + g + 8) * 36 + base + 4];
        }

        float c[8][4];
        #pragma unroll
        for (int nt = 0; nt < 8; nt++)
            #pragma unroll
            for (int q = 0; q < 4; q++) c[nt][q] = 0.0f;

        #pragma unroll
        for (int nt = 0; nt < 8; nt++) {
            int nb = (nt * 8 + g) * 36 + tq;
            u32 b00 = Bs32[nb],      b01 = Bs32[nb + 4];
            u32 b10 = Bs32[nb + 8],  b11 = Bs32[nb + 12];
            u32 b20 = Bs32[nb + 16], b21 = Bs32[nb + 20];
            u32 b30 = Bs32[nb + 24], b31 = Bs32[nb + 28];
            mma16816(c[nt], aa[0], b00, b01);   // hi*hi
            mma16816(c[nt], aa[1], b10, b11);
            mma16816(c[nt], aa[0], b20, b21);   // hi*lo
            mma16816(c[nt], aa[1], b30, b31);
            mma16816(c[nt], aa[2], b00, b01);   // lo*hi
            mma16816(c[nt], aa[3], b10, b11);
        }
        __syncthreads();   // all A smem reads done -> stg may overwrite A

        // epilogue in place: bias + selu + per-head abs row sums
        float s0g = 0.f, s0h = 0.f, s1g = 0.f, s1h = 0.f;
        #pragma unroll
        for (int nt = 0; nt < 8; nt++) {
            float b0v = bhs[nt * 8 + 2 * tq];
            float b1v = bhs[nt * 8 + 2 * tq + 1];
            c[nt][0] = selu_f(c[nt][0] + b0v);
            c[nt][1] = selu_f(c[nt][1] + b1v);
            c[nt][2] = selu_f(c[nt][2] + b0v);
            c[nt][3] = selu_f(c[nt][3] + b1v);
            if (nt < 4) { s0g += fabsf(c[nt][0]) + fabsf(c[nt][1]);
                          s0h += fabsf(c[nt][2]) + fabsf(c[nt][3]); }
            else        { s1g += fabsf(c[nt][0]) + fabsf(c[nt][1]);
                          s1h += fabsf(c[nt][2]) + fabsf(c[nt][3]); }
        }
        s0g += __shfl_xor_sync(0xFFFFFFFF, s0g, 1);
        s0g += __shfl_xor_sync(0xFFFFFFFF, s0g, 2);
        s0h += __shfl_xor_sync(0xFFFFFFFF, s0h, 1);
        s0h += __shfl_xor_sync(0xFFFFFFFF, s0h, 2);
        s1g += __shfl_xor_sync(0xFFFFFFFF, s1g, 1);
        s1g += __shfl_xor_sync(0xFFFFFFFF, s1g, 2);
        s1h += __shfl_xor_sync(0xFFFFFFFF, s1h, 1);
        s1h += __shfl_xor_sync(0xFFFFFFFF, s1h, 2);
        float inv0g = __fdividef(1.0f, fmaxf(s0g, 1e-12f));
        float inv0h = __fdividef(1.0f, fmaxf(s0h, 1e-12f));
        float inv1g = __fdividef(1.0f, fmaxf(s1g, 1e-12f));
        float inv1h = __fdividef(1.0f, fmaxf(s1h, 1e-12f));
        #pragma unroll
        for (int nt = 0; nt < 8; nt++) {
            float ig = (nt < 4) ? inv0g : inv1g;
            float ih = (nt < 4) ? inv0h : inv1h;
            c[nt][0] *= ig; c[nt][1] *= ig;    // sign(d)*|d|/l1 == d/l1
            c[nt][2] *= ih; c[nt][3] *= ih;
        }

        // two 64-row halves: owning warps stage compact (head1 at col 25), all store
        #pragma unroll
        for (int half = 0; half < 2; half++) {
            if (halfw == half) {
                #pragma unroll
                for (int nt = 0; nt < 8; nt++) {
                    int ncol = nt * 8 + 2 * tq;
                    int bj   = (nt < 4) ? ncol : (ncol - 32);
                    int dcol = (nt < 4) ? ncol : (E_N + (ncol - 32));
                    if (bj < E_N) {
                        stg[lr0 * 68 + dcol]       = c[nt][0];
                        stg[(lr0 + 8) * 68 + dcol] = c[nt][2];
                    }
                    if (bj + 1 < E_N) {
                        stg[lr0 * 68 + dcol + 1]       = c[nt][1];
                        stg[(lr0 + 8) * 68 + dcol + 1] = c[nt][3];
                    }
                }
            }
            __syncthreads();
            float* ob = out + (size_t)(row0 + 64 * half) * (HG * E_N)
                            + band * 200 + hp * 50;
            for (int i = t; i < 64 * 25; i += 256) {
                int r = i / 25, c2 = i - r * 25;
                float2 v = make_float2(stg[r * 68 + 2 * c2], stg[r * 68 + 2 * c2 + 1]);
                *(float2*)(ob + (size_t)r * (HG * E_N) + 2 * c2) = v;   // 8B aligned
            }
            __syncthreads();
        }
        row0 += 128;
    }
}

// ---------------------------------------------------------------------------
extern "C" void kernel_launch(void* const* d_in, const int* in_sizes, int n_in,
                              void* d_out, int out_size) {
    const float* X     = (const float*)d_in[0];
    const float* W1    = (const float*)d_in[1];
    const float* b1    = (const float*)d_in[2];
    const float* W2    = (const float*)d_in[3];
    const float* b2    = (const float*)d_in[4];
    const float* gamma = (const float*)d_in[5];
    const float* beta  = (const float*)d_in[6];
    const float* Wh    = (const float*)d_in[7];
    const float* bh    = (const float*)d_in[8];
    float* out = (float*)d_out;

    cudaFuncSetAttribute(kernA, cudaFuncAttributeMaxDynamicSharedMemorySize, 25856);
    cudaFuncSetAttribute(kernC, cudaFuncAttributeMaxDynamicSharedMemorySize, 27904);

    kernA<<<1024, 128, 25856>>>(X, W1, b1, W2, b2);
    kernBW<<<13, 256>>>(gamma, beta, Wh);
    kernE<<<512, 128>>>();
    kernC<<<dim3(48, 64), 256, 27904>>>(bh, out);
}